// round 14
// baseline (speedup 1.0000x reference)
#include <cuda_runtime.h>

#define KAPn 8
#define Nn   2000
#define NPn  2048
#define N0n  1000
#define Mn   10000
#define Dn   8
#define NBn  128
#define NSTEPS 16        // NPn / NBn
#define NUGf 1e-6f
#define KCH  32          // syrk k-chunk

// ---------------- device scratch (static, no runtime allocation) ----------------
__device__ float g_K[KAPn * NPn * NPn];     // padded covariance / Cholesky factors
__device__ float g_Knt[KAPn * N0n * Nn];    // cross covariance
__device__ float g_rhs[KAPn * NPn];         // rhs -> alpha (in place)
__device__ float g_invd[KAPn * NPn];        // 1 / L[j][j]
__device__ float g_ghat[KAPn * N0n];

__device__ __forceinline__ float warp_reduce(float v) {
#pragma unroll
    for (int s = 16; s > 0; s >>= 1) v += __shfl_xor_sync(0xffffffffu, v, s);
    return v;
}

// packed dual-fp32 FMA (Blackwell f32x2; ptxas never auto-emits this)
__device__ __forceinline__ void ffma2(unsigned long long& d,
                                      unsigned long long a,
                                      unsigned long long b) {
    asm("fma.rn.f32x2 %0, %1, %2, %0;" : "+l"(d) : "l"(a), "l"(b));
}
__device__ __forceinline__ unsigned long long splat2(float x) {
    unsigned long long r;
    asm("mov.b64 %0, {%1, %1};" : "=l"(r) : "f"(x));
    return r;
}
__device__ __forceinline__ void unpack2(unsigned long long v, float& lo, float& hi) {
    asm("mov.b64 {%0, %1}, %2;" : "=f"(lo), "=f"(hi) : "l"(v));
}

// exp(-s) for s >= 0, FMA-pipe only (no MUFU). |rel err| ~3e-7.
__device__ __forceinline__ float fast_expn(float s) {
    float z = s * -1.4426950408889634f;          // log2(e)
    z = fmaxf(z, -125.0f);                       // underflow guard
    int e = __float2int_rn(z);
    float f = z - (float)e;                      // f in [-0.5, 0.5]
    float p = fmaf(f, 1.5403530e-4f, 1.3333558e-3f);
    p = fmaf(f, p, 9.6181291e-3f);
    p = fmaf(f, p, 5.5504109e-2f);
    p = fmaf(f, p, 2.4022651e-1f);
    p = fmaf(f, p, 6.9314718e-1f);
    p = fmaf(f, p, 1.0f);
    return p * __int_as_float((e + 127) << 23);
}

// ---------------- build K_tt (padded to 2048 with identity) ----------------
__global__ void build_ktt_kernel(const float* __restrict__ theta,
                                 const float* __restrict__ Lmb) {
    int kap = blockIdx.z;
    int i = blockIdx.y * 16 + threadIdx.y;
    int j = blockIdx.x * 16 + threadIdx.x;
    __shared__ float ti[16][Dn], tj[16][Dn];
    __shared__ float s_ils[Dn];
    __shared__ float s_amp;
    int t = threadIdx.y * 16 + threadIdx.x;
    if (t < 16 * Dn) {
        int r = t / Dn, d = t % Dn;
        int gi = blockIdx.y * 16 + r;
        ti[r][d] = (gi < Nn) ? theta[gi * Dn + d] : 0.f;
        int gj = blockIdx.x * 16 + r;
        tj[r][d] = (gj < Nn) ? theta[gj * Dn + d] : 0.f;
    }
    if (threadIdx.y == 15) {
        if (threadIdx.x < Dn) s_ils[threadIdx.x] = expf(-Lmb[kap * (Dn + 1) + threadIdx.x]);
        if (threadIdx.x == Dn) s_amp = expf(Lmb[kap * (Dn + 1) + Dn]);
    }
    __syncthreads();
    float v;
    if (i < Nn && j < Nn) {
        float prod = 1.f, ssum = 0.f;
#pragma unroll
        for (int d = 0; d < Dn; d++) {
            float S = fabsf(ti[threadIdx.y][d] - tj[threadIdx.x][d]) * s_ils[d];
            prod *= (1.f + S);
            ssum += S;
        }
        v = s_amp * prod * fast_expn(ssum);
        if (i == j) v += NUGf * s_amp;
    } else {
        v = (i == j) ? 1.f : 0.f;
    }
    g_K[(size_t)kap * NPn * NPn + (size_t)i * NPn + j] = v;
}

// ---------------- build K_nt ----------------
__global__ void build_knt_kernel(const float* __restrict__ theta0,
                                 const float* __restrict__ theta,
                                 const float* __restrict__ Lmb) {
    int kap = blockIdx.z;
    int o = blockIdx.y * 16 + threadIdx.y;
    int n = blockIdx.x * 16 + threadIdx.x;
    __shared__ float to_[16][Dn], tn_[16][Dn];
    __shared__ float s_ils[Dn];
    __shared__ float s_amp;
    int t = threadIdx.y * 16 + threadIdx.x;
    if (t < 16 * Dn) {
        int r = t / Dn, d = t % Dn;
        int go = blockIdx.y * 16 + r;
        to_[r][d] = (go < N0n) ? theta0[go * Dn + d] : 0.f;
        int gn = blockIdx.x * 16 + r;
        tn_[r][d] = (gn < Nn) ? theta[gn * Dn + d] : 0.f;
    }
    if (threadIdx.y == 15) {
        if (threadIdx.x < Dn) s_ils[threadIdx.x] = expf(-Lmb[kap * (Dn + 1) + threadIdx.x]);
        if (threadIdx.x == Dn) s_amp = expf(Lmb[kap * (Dn + 1) + Dn]);
    }
    __syncthreads();
    if (o >= N0n || n >= Nn) return;
    float prod = 1.f, ssum = 0.f;
#pragma unroll
    for (int d = 0; d < Dn; d++) {
        float S = fabsf(to_[threadIdx.y][d] - tn_[threadIdx.x][d]) * s_ils[d];
        prod *= (1.f + S);
        ssum += S;
    }
    g_Knt[(size_t)(kap * N0n + o) * Nn + n] = s_amp * prod * fast_expn(ssum);
}

// ---------------- rhs init ----------------
__global__ void init_rhs_kernel(const float* __restrict__ Mu) {
    int idx = blockIdx.x * blockDim.x + threadIdx.x;
    if (idx >= KAPn * NPn) return;
    int kap = idx / NPn, i = idx % NPn;
    g_rhs[idx] = (i < Nn) ? Mu[kap * Nn + i] : 0.f;
}

// ---------------- potf2 v2: 32-wide recursive blocking -----------------------
// 4 sub-steps of: chol32 (warp 0, syncwarp only) -> in-block trsm (16 warps,
// shfl substitution) -> in-block rank-32 syrk (512 threads). ~14 block barriers
// total instead of 128.
__global__ void __launch_bounds__(512) potf2_kernel(const float* __restrict__ Lmb, int off) {
    extern __shared__ float sm[];
    float* sh = sm;                  // [128][129]
    float* sdi = sm + NBn * (NBn + 1);
    int kap = blockIdx.x;
    int tid = threadIdx.x;
    float* A = g_K + (size_t)kap * NPn * NPn + (size_t)off * NPn + off;
    for (int fi = tid; fi < 4096; fi += 512) {        // 128x128 in float4s
        int r = fi >> 5;
        int c4 = (fi & 31) * 4;
        float4 v = *(const float4*)(A + (size_t)r * NPn + c4);
        float* shr = sh + r * (NBn + 1) + c4;
        shr[0] = v.x; shr[1] = v.y; shr[2] = v.z; shr[3] = v.w;
    }
    __shared__ float s_dmin;
    if (tid == 0) s_dmin = 1e-4f * expf(Lmb[kap * (Dn + 1) + Dn]);
    __syncthreads();
    float dmin = s_dmin;

    for (int s = 0; s < 4; s++) {
        int c0 = s * 32;
        // ---- chol32: warp 0, deferred scaling, syncwarp-only ----
        if (tid < 32) {
            int l = tid;
            for (int j = 0; j < 32; j++) {
                float d = sh[(c0 + j) * (NBn + 1) + c0 + j];
                if (!(d > dmin)) d = dmin;
                float rinv = rsqrtf(d);
                __syncwarp();
                if (l == j) { sh[(c0 + j) * (NBn + 1) + c0 + j] = d; sdi[c0 + j] = rinv; }
                if (l > j) {
                    float ltj = sh[(c0 + l) * (NBn + 1) + c0 + j] * (rinv * rinv);
                    for (int i = j + 1; i <= l; i++)
                        sh[(c0 + l) * (NBn + 1) + c0 + i] -= ltj * sh[(c0 + i) * (NBn + 1) + c0 + j];
                }
                __syncwarp();
            }
            // scale own row: cols j <= l (diag becomes sqrt(d))
            for (int j = 0; j <= l; j++)
                sh[(c0 + l) * (NBn + 1) + c0 + j] *= sdi[c0 + j];
        }
        __syncthreads();

        int R = NBn - c0 - 32;            // in-block rows below
        if (R > 0) {
            // ---- trsm: 16 warps, nr rows each, lane = col ----
            int nr = R >> 4;              // 6 / 4 / 2
            int w = tid >> 5, lane = tid & 31;
            int row0 = c0 + 32 + w * nr;
            float x[6];
#pragma unroll
            for (int rr = 0; rr < 6; rr++)
                if (rr < nr) x[rr] = sh[(row0 + rr) * (NBn + 1) + c0 + lane];
            for (int j = 0; j < 32; j++) {
                float sv = sdi[c0 + j];
                float Lcol = sh[(c0 + lane) * (NBn + 1) + c0 + j];  // L[lane][j], lane>j
#pragma unroll
                for (int rr = 0; rr < 6; rr++) {
                    if (rr < nr) {
                        if (lane == j) x[rr] *= sv;
                        float xj = __shfl_sync(0xffffffffu, x[rr], j);
                        if (lane > j) x[rr] -= xj * Lcol;
                    }
                }
            }
#pragma unroll
            for (int rr = 0; rr < 6; rr++)
                if (rr < nr) sh[(row0 + rr) * (NBn + 1) + c0 + lane] = x[rr];
            __syncthreads();

            // ---- rank-32 syrk of trailing in-block region ----
            int t = tid & 127, q = tid >> 7;
            if (t >= c0 + 32) {
                float Lt[32];
#pragma unroll
                for (int j = 0; j < 32; j++) Lt[j] = sh[t * (NBn + 1) + c0 + j];
                int ilo = q * 32; if (ilo < c0 + 32) ilo = c0 + 32;
                int ihi = q * 32 + 31; if (ihi > t) ihi = t;
                for (int i = ilo; i <= ihi; i++) {
                    float acc = 0.f;
#pragma unroll
                    for (int j = 0; j < 32; j++) acc += Lt[j] * sh[i * (NBn + 1) + c0 + j];
                    sh[t * (NBn + 1) + i] -= acc;
                }
            }
            __syncthreads();
        }
    }

    for (int fi = tid; fi < 4096; fi += 512) {
        int r = fi >> 5;
        int c4 = (fi & 31) * 4;
        const float* shr = sh + r * (NBn + 1) + c4;
        float4 v = make_float4(shr[0], shr[1], shr[2], shr[3]);
        *(float4*)(A + (size_t)r * NPn + c4) = v;
    }
    if (tid < NBn) g_invd[kap * NPn + off + tid] = sdi[tid];
}

// ---------------- Cholesky panel trsm: L21 = A21 * L11^{-T} ----------------
// 64 rows per CTA (8 warps x 8 rows): halves grid + L11 staging traffic vs 32.
__global__ void __launch_bounds__(256) trsm_kernel(int off, int m) {
    extern __shared__ float sm[];
    float* Ls = sm;                  // [128][129]
    float* sinv = sm + NBn * (NBn + 1);
    int kap = blockIdx.y;
    int tid = threadIdx.x;
    float* G = g_K + (size_t)kap * NPn * NPn;
    const float* L11 = G + (size_t)off * NPn + off;
    for (int idx = tid; idx < NBn * NBn; idx += 256) {
        int r = idx >> 7, c = idx & 127;
        Ls[r * (NBn + 1) + c] = L11[r * NPn + c];
    }
    if (tid < NBn) sinv[tid] = g_invd[kap * NPn + off + tid];
    __syncthreads();
    int w = tid >> 5, lane = tid & 31;
    int row0 = off + NBn + blockIdx.x * 64 + w * 8;
    float x[8][4];                   // [row][quarter]
#pragma unroll
    for (int rr = 0; rr < 8; rr++) {
        const float* arow = G + (size_t)(row0 + rr) * NPn + off;
#pragma unroll
        for (int qq = 0; qq < 4; qq++) x[rr][qq] = arow[lane + 32 * qq];
    }
#pragma unroll
    for (int qj = 0; qj < 4; qj++) {
#pragma unroll
        for (int lj = 0; lj < 32; lj++) {
            int j = qj * 32 + lj;
            float sv = sinv[j];
            if (lane == lj) {
#pragma unroll
                for (int rr = 0; rr < 8; rr++) x[rr][qj] *= sv;
            }
            float xj[8];
#pragma unroll
            for (int rr = 0; rr < 8; rr++) xj[rr] = __shfl_sync(0xffffffffu, x[rr][qj], lj);
#pragma unroll
            for (int qq = qj; qq < 4; qq++) {
                float Lv = Ls[(lane + 32 * qq) * (NBn + 1) + j];
                bool act = (qq > qj) || (lane > lj);
                if (act) {
#pragma unroll
                    for (int rr = 0; rr < 8; rr++) x[rr][qq] -= xj[rr] * Lv;
                }
            }
        }
    }
#pragma unroll
    for (int rr = 0; rr < 8; rr++) {
        float* arow = G + (size_t)(row0 + rr) * NPn + off;
#pragma unroll
        for (int qq = 0; qq < 4; qq++) arow[lane + 32 * qq] = x[rr][qq];
    }
}

// ---------------- SYRK: conflict-free micro-tile + packed f32x2 FMA ----------
__global__ void __launch_bounds__(256, 2) syrk_kernel(int off, int nb) {
    int kap = blockIdx.y;
    int tt = blockIdx.x;
    int bi = 0, rem = tt;
    while (rem > bi) { rem -= (bi + 1); bi++; }
    int bj = rem;                     // bi >= bj
    int r0 = off + NBn;
    int R = r0 + bi * NBn, C = r0 + bj * NBn;
    float* G = g_K + (size_t)kap * NPn * NPn;

    __shared__ float As[KCH][NBn + 4];
    __shared__ float Bs[KCH][NBn + 4];
    unsigned long long acc2[8][4];
#pragma unroll
    for (int m = 0; m < 8; m++)
#pragma unroll
        for (int p = 0; p < 4; p++) acc2[m][p] = 0ull;

    int tid = threadIdx.x;
    int tr = tid >> 4, tc = tid & 15;

    for (int kk = 0; kk < NBn; kk += KCH) {
#pragma unroll
        for (int s = 0; s < 4; s++) {
            int fi = tid + s * 256;       // float4 index in [0,1024)
            int row = fi >> 3;
            int kq = (fi & 7) * 4;
            float4 av = *(const float4*)(G + (size_t)(R + row) * NPn + off + kk + kq);
            As[kq + 0][row] = av.x; As[kq + 1][row] = av.y;
            As[kq + 2][row] = av.z; As[kq + 3][row] = av.w;
            float4 bv = *(const float4*)(G + (size_t)(C + row) * NPn + off + kk + kq);
            Bs[kq + 0][row] = bv.x; Bs[kq + 1][row] = bv.y;
            Bs[kq + 2][row] = bv.z; Bs[kq + 3][row] = bv.w;
        }
        __syncthreads();
#pragma unroll
        for (int k = 0; k < KCH; k++) {
            float4 a0 = *(const float4*)&As[k][tr * 8];
            float4 a1 = *(const float4*)&As[k][tr * 8 + 4];
            ulonglong2 bl = *(const ulonglong2*)&Bs[k][tc * 4];
            ulonglong2 bh = *(const ulonglong2*)&Bs[k][tc * 4 + 64];
            float ar[8] = {a0.x, a0.y, a0.z, a0.w, a1.x, a1.y, a1.z, a1.w};
#pragma unroll
            for (int m = 0; m < 8; m++) {
                unsigned long long am = splat2(ar[m]);
                ffma2(acc2[m][0], am, bl.x);
                ffma2(acc2[m][1], am, bl.y);
                ffma2(acc2[m][2], am, bh.x);
                ffma2(acc2[m][3], am, bh.y);
            }
        }
        __syncthreads();
    }
#pragma unroll
    for (int m = 0; m < 8; m++) {
        float* rowp = G + (size_t)(R + tr * 8 + m) * NPn + C;
        float4* p0 = (float4*)(rowp + tc * 4);
        float4* p1 = (float4*)(rowp + tc * 4 + 64);
        float4 v0 = *p0, v1 = *p1;
        float e0, e1, e2, e3;
        unpack2(acc2[m][0], e0, e1); unpack2(acc2[m][1], e2, e3);
        v0.x -= e0; v0.y -= e1; v0.z -= e2; v0.w -= e3;
        unpack2(acc2[m][2], e0, e1); unpack2(acc2[m][3], e2, e3);
        v1.x -= e0; v1.y -= e1; v1.z -= e2; v1.w -= e3;
        *p0 = v0; *p1 = v1;
    }
}

// ---------------- fused forward solve: L y = rhs (one CTA per kap) ----------
__global__ void __launch_bounds__(1024) fwd_solve_kernel() {
    extern __shared__ float sm[];
    float* Ls = sm;                               // [128][129]
    float* sinv = sm + NBn * (NBn + 1);           // [128]
    float* sr = sinv + NBn;                       // [2048]
    int kap = blockIdx.x;
    int tid = threadIdx.x;
    const float* G = g_K + (size_t)kap * NPn * NPn;
    float* r = g_rhs + kap * NPn;
    for (int i = tid; i < NPn; i += 1024) sr[i] = r[i];
    for (int k = 0; k < NSTEPS; k++) {
        int off = k * NBn;
        const float* L11 = G + (size_t)off * NPn + off;
        for (int idx = tid; idx < NBn * NBn; idx += 1024) {
            int rr = idx >> 7, c = idx & 127;
            Ls[rr * (NBn + 1) + c] = L11[rr * NPn + c];
        }
        if (tid < NBn) sinv[tid] = g_invd[kap * NPn + off + tid];
        __syncthreads();
        if (tid < 32) {
            int lane = tid;
            float x[4];
#pragma unroll
            for (int qq = 0; qq < 4; qq++) x[qq] = sr[off + lane + 32 * qq];
#pragma unroll
            for (int qj = 0; qj < 4; qj++) {
#pragma unroll
                for (int lj = 0; lj < 32; lj++) {
                    int j = qj * 32 + lj;
                    if (lane == lj) x[qj] *= sinv[j];
                    float xj = __shfl_sync(0xffffffffu, x[qj], lj);
                    if (lane > lj) x[qj] -= xj * Ls[(lane + 32 * qj) * (NBn + 1) + j];
#pragma unroll
                    for (int qq = qj + 1; qq < 4; qq++)
                        x[qq] -= xj * Ls[(lane + 32 * qq) * (NBn + 1) + j];
                }
            }
#pragma unroll
            for (int qq = 0; qq < 4; qq++) sr[off + lane + 32 * qq] = x[qq];
        }
        __syncthreads();
        // update rows below: 4 rows in flight per warp (MLP=4), m % 128 == 0
        int wid = tid >> 5, lane = tid & 31;
        const float4* srv = (const float4*)(sr + off);
        float4 b = srv[lane];
        for (int row = off + NBn + wid; row < NPn; row += 128) {
            float4 a0 = ((const float4*)(G + (size_t)row * NPn + off))[lane];
            float4 a1 = ((const float4*)(G + (size_t)(row + 32) * NPn + off))[lane];
            float4 a2 = ((const float4*)(G + (size_t)(row + 64) * NPn + off))[lane];
            float4 a3 = ((const float4*)(G + (size_t)(row + 96) * NPn + off))[lane];
            float s0 = a0.x * b.x + a0.y * b.y + a0.z * b.z + a0.w * b.w;
            float s1 = a1.x * b.x + a1.y * b.y + a1.z * b.z + a1.w * b.w;
            float s2 = a2.x * b.x + a2.y * b.y + a2.z * b.z + a2.w * b.w;
            float s3 = a3.x * b.x + a3.y * b.y + a3.z * b.z + a3.w * b.w;
#pragma unroll
            for (int s = 16; s > 0; s >>= 1) {
                s0 += __shfl_xor_sync(0xffffffffu, s0, s);
                s1 += __shfl_xor_sync(0xffffffffu, s1, s);
                s2 += __shfl_xor_sync(0xffffffffu, s2, s);
                s3 += __shfl_xor_sync(0xffffffffu, s3, s);
            }
            if (lane == 0) {
                sr[row] -= s0;
                sr[row + 32] -= s1;
                sr[row + 64] -= s2;
                sr[row + 96] -= s3;
            }
        }
        __syncthreads();
    }
    for (int i = tid; i < NPn; i += 1024) r[i] = sr[i];
}

// ---------------- fused backward solve: L^T x = y (one CTA per kap) ---------
__global__ void __launch_bounds__(1024) bwd_solve_kernel() {
    extern __shared__ float sm[];
    float* Ls = sm;
    float* sinv = sm + NBn * (NBn + 1);
    float* sr = sinv + NBn;
    int kap = blockIdx.x;
    int tid = threadIdx.x;
    const float* G = g_K + (size_t)kap * NPn * NPn;
    float* r = g_rhs + kap * NPn;
    for (int i = tid; i < NPn; i += 1024) sr[i] = r[i];
    for (int k = NSTEPS - 1; k >= 0; k--) {
        int off = k * NBn;
        const float* L11 = G + (size_t)off * NPn + off;
        for (int idx = tid; idx < NBn * NBn; idx += 1024) {
            int rr = idx >> 7, c = idx & 127;
            Ls[rr * (NBn + 1) + c] = L11[rr * NPn + c];
        }
        if (tid < NBn) sinv[tid] = g_invd[kap * NPn + off + tid];
        __syncthreads();
        if (tid < 32) {
            int lane = tid;
            float x[4];
#pragma unroll
            for (int qq = 0; qq < 4; qq++) x[qq] = sr[off + lane + 32 * qq];
#pragma unroll
            for (int qj = 3; qj >= 0; qj--) {
#pragma unroll
                for (int lj = 31; lj >= 0; lj--) {
                    int j = qj * 32 + lj;
                    if (lane == lj) x[qj] *= sinv[j];
                    float xj = __shfl_sync(0xffffffffu, x[qj], lj);
                    if (lane < lj) x[qj] -= xj * Ls[j * (NBn + 1) + lane + 32 * qj];
#pragma unroll
                    for (int qq = 0; qq < qj; qq++)
                        x[qq] -= xj * Ls[j * (NBn + 1) + lane + 32 * qq];
                }
            }
#pragma unroll
            for (int qq = 0; qq < 4; qq++) sr[off + lane + 32 * qq] = x[qq];
        }
        __syncthreads();
        float4* srv = (float4*)sr;
        for (int c4 = tid; c4 < off / 4; c4 += 1024) {
            const float4* col = (const float4*)(G + (size_t)off * NPn) + c4;
            float4 s = make_float4(0.f, 0.f, 0.f, 0.f);
#pragma unroll 8
            for (int i = 0; i < NBn; i++) {
                float4 v = col[(size_t)i * (NPn / 4)];
                float xv = sr[off + i];
                s.x += v.x * xv; s.y += v.y * xv; s.z += v.z * xv; s.w += v.w * xv;
            }
            float4 cur = srv[c4];
            cur.x -= s.x; cur.y -= s.y; cur.z -= s.z; cur.w -= s.w;
            srv[c4] = cur;
        }
        __syncthreads();
    }
    for (int i = tid; i < NPn; i += 1024) r[i] = sr[i];
}

// ---------------- ghat = K_nt @ alpha (warp per output) ----------------
__global__ void ghat_kernel() {
    int gw = (blockIdx.x * blockDim.x + threadIdx.x) >> 5;
    int lane = threadIdx.x & 31;
    if (gw >= KAPn * N0n) return;
    int kap = gw / N0n, o = gw % N0n;
    const float* Kr = g_Knt + (size_t)(kap * N0n + o) * Nn;
    const float* a = g_rhs + kap * NPn;
    float s = 0.f;
    for (int i = lane * 4; i < Nn; i += 128) {
        float4 kv = *(const float4*)(Kr + i);
        float4 av = *(const float4*)(a + i);
        s += kv.x * av.x + kv.y * av.y + kv.z * av.z + kv.w * av.w;
    }
    s = warp_reduce(s);
    if (lane == 0) g_ghat[kap * N0n + o] = s;
}

// ---------------- fhat = psi + Phi @ ghat ----------------
__global__ void fhat_kernel(const float* __restrict__ psi,
                            const float* __restrict__ Phi,
                            float* __restrict__ out) {
    int idx = blockIdx.x * blockDim.x + threadIdx.x;
    if (idx >= Mn * N0n) return;
    int m = idx / N0n, o = idx % N0n;
    float s = psi[m];
#pragma unroll
    for (int k = 0; k < KAPn; k++) s += Phi[m * KAPn + k] * g_ghat[k * N0n + o];
    out[idx] = s;
}

// ---------------- host launch ----------------
extern "C" void kernel_launch(void* const* d_in, const int* in_sizes, int n_in,
                              void* d_out, int out_size) {
    const float* theta0 = (const float*)d_in[0];
    const float* Lmb    = (const float*)d_in[1];
    // d_in[2] = lsigma2 (unused by fhat)
    const float* Mu     = (const float*)d_in[3];
    const float* psi    = (const float*)d_in[4];
    const float* Phi    = (const float*)d_in[5];
    const float* theta  = (const float*)d_in[6];
    float* out = (float*)d_out;

    const int SMEM_FACT  = (NBn * (NBn + 1) + NBn) * (int)sizeof(float);          // 66560
    const int SMEM_SOLVE = (NBn * (NBn + 1) + NBn + NPn) * (int)sizeof(float);    // 74752
    cudaFuncSetAttribute(potf2_kernel,     cudaFuncAttributeMaxDynamicSharedMemorySize, SMEM_FACT);
    cudaFuncSetAttribute(trsm_kernel,      cudaFuncAttributeMaxDynamicSharedMemorySize, SMEM_FACT);
    cudaFuncSetAttribute(fwd_solve_kernel, cudaFuncAttributeMaxDynamicSharedMemorySize, SMEM_SOLVE);
    cudaFuncSetAttribute(bwd_solve_kernel, cudaFuncAttributeMaxDynamicSharedMemorySize, SMEM_SOLVE);

    // Launch order: #4 = potf2 step 0 (the profiled launch — measure the v2 rewrite).
    build_ktt_kernel<<<dim3(NPn / 16, NPn / 16, KAPn), dim3(16, 16)>>>(theta, Lmb);
    build_knt_kernel<<<dim3((Nn + 15) / 16, (N0n + 15) / 16, KAPn), dim3(16, 16)>>>(theta0, theta, Lmb);
    init_rhs_kernel<<<(KAPn * NPn + 255) / 256, 256>>>(Mu);

    for (int k = 0; k < NSTEPS; k++) {
        int off = k * NBn;
        potf2_kernel<<<KAPn, 512, SMEM_FACT>>>(Lmb, off);   // k==0 -> launch #4
        int m = NPn - off - NBn;
        if (m > 0) {
            trsm_kernel<<<dim3(m / 64, KAPn), 256, SMEM_FACT>>>(off, m);
            int nb = m / NBn;
            syrk_kernel<<<dim3(nb * (nb + 1) / 2, KAPn), 256>>>(off, nb);
        }
    }

    fwd_solve_kernel<<<KAPn, 1024, SMEM_SOLVE>>>();
    bwd_solve_kernel<<<KAPn, 1024, SMEM_SOLVE>>>();

    ghat_kernel<<<(KAPn * N0n * 32 + 255) / 256, 256>>>();
    fhat_kernel<<<(Mn * N0n + 255) / 256, 256>>>(psi, Phi, out);
}

// round 15
// speedup vs baseline: 1.3005x; 1.3005x over previous
#include <cuda_runtime.h>

#define KAPn 8
#define Nn   2000
#define NPn  2048
#define N0n  1000
#define Mn   10000
#define Dn   8
#define NBn  128
#define NSTEPS 16        // NPn / NBn
#define NUGf 1e-6f
#define KCH  32          // syrk k-chunk

// ---------------- device scratch (static, no runtime allocation) ----------------
__device__ float g_K[KAPn * NPn * NPn];     // padded covariance / Cholesky factors
__device__ float g_Knt[KAPn * N0n * Nn];    // cross covariance
__device__ float g_rhs[KAPn * NPn];         // rhs -> alpha (in place)
__device__ float g_invd[KAPn * NPn];        // 1 / L[j][j]
__device__ float g_ghat[KAPn * N0n];

__device__ __forceinline__ float warp_reduce(float v) {
#pragma unroll
    for (int s = 16; s > 0; s >>= 1) v += __shfl_xor_sync(0xffffffffu, v, s);
    return v;
}

// packed dual-fp32 FMA (Blackwell f32x2; ptxas never auto-emits this)
__device__ __forceinline__ void ffma2(unsigned long long& d,
                                      unsigned long long a,
                                      unsigned long long b) {
    asm("fma.rn.f32x2 %0, %1, %2, %0;" : "+l"(d) : "l"(a), "l"(b));
}
__device__ __forceinline__ unsigned long long splat2(float x) {
    unsigned long long r;
    asm("mov.b64 %0, {%1, %1};" : "=l"(r) : "f"(x));
    return r;
}
__device__ __forceinline__ void unpack2(unsigned long long v, float& lo, float& hi) {
    asm("mov.b64 {%0, %1}, %2;" : "=f"(lo), "=f"(hi) : "l"(v));
}

// exp(-s) for s >= 0, FMA-pipe only (no MUFU). |rel err| ~3e-7.
__device__ __forceinline__ float fast_expn(float s) {
    float z = s * -1.4426950408889634f;          // log2(e)
    z = fmaxf(z, -125.0f);                       // underflow guard
    int e = __float2int_rn(z);
    float f = z - (float)e;                      // f in [-0.5, 0.5]
    float p = fmaf(f, 1.5403530e-4f, 1.3333558e-3f);
    p = fmaf(f, p, 9.6181291e-3f);
    p = fmaf(f, p, 5.5504109e-2f);
    p = fmaf(f, p, 2.4022651e-1f);
    p = fmaf(f, p, 6.9314718e-1f);
    p = fmaf(f, p, 1.0f);
    return p * __int_as_float((e + 127) << 23);
}

// ---------------- build K_tt (padded to 2048 with identity) ----------------
__global__ void build_ktt_kernel(const float* __restrict__ theta,
                                 const float* __restrict__ Lmb) {
    int kap = blockIdx.z;
    int i = blockIdx.y * 16 + threadIdx.y;
    int j = blockIdx.x * 16 + threadIdx.x;
    __shared__ float ti[16][Dn], tj[16][Dn];
    __shared__ float s_ils[Dn];
    __shared__ float s_amp;
    int t = threadIdx.y * 16 + threadIdx.x;
    if (t < 16 * Dn) {
        int r = t / Dn, d = t % Dn;
        int gi = blockIdx.y * 16 + r;
        ti[r][d] = (gi < Nn) ? theta[gi * Dn + d] : 0.f;
        int gj = blockIdx.x * 16 + r;
        tj[r][d] = (gj < Nn) ? theta[gj * Dn + d] : 0.f;
    }
    if (threadIdx.y == 15) {
        if (threadIdx.x < Dn) s_ils[threadIdx.x] = expf(-Lmb[kap * (Dn + 1) + threadIdx.x]);
        if (threadIdx.x == Dn) s_amp = expf(Lmb[kap * (Dn + 1) + Dn]);
    }
    __syncthreads();
    float v;
    if (i < Nn && j < Nn) {
        float prod = 1.f, ssum = 0.f;
#pragma unroll
        for (int d = 0; d < Dn; d++) {
            float S = fabsf(ti[threadIdx.y][d] - tj[threadIdx.x][d]) * s_ils[d];
            prod *= (1.f + S);
            ssum += S;
        }
        v = s_amp * prod * fast_expn(ssum);
        if (i == j) v += NUGf * s_amp;
    } else {
        v = (i == j) ? 1.f : 0.f;
    }
    g_K[(size_t)kap * NPn * NPn + (size_t)i * NPn + j] = v;
}

// ---------------- build K_nt ----------------
__global__ void build_knt_kernel(const float* __restrict__ theta0,
                                 const float* __restrict__ theta,
                                 const float* __restrict__ Lmb) {
    int kap = blockIdx.z;
    int o = blockIdx.y * 16 + threadIdx.y;
    int n = blockIdx.x * 16 + threadIdx.x;
    __shared__ float to_[16][Dn], tn_[16][Dn];
    __shared__ float s_ils[Dn];
    __shared__ float s_amp;
    int t = threadIdx.y * 16 + threadIdx.x;
    if (t < 16 * Dn) {
        int r = t / Dn, d = t % Dn;
        int go = blockIdx.y * 16 + r;
        to_[r][d] = (go < N0n) ? theta0[go * Dn + d] : 0.f;
        int gn = blockIdx.x * 16 + r;
        tn_[r][d] = (gn < Nn) ? theta[gn * Dn + d] : 0.f;
    }
    if (threadIdx.y == 15) {
        if (threadIdx.x < Dn) s_ils[threadIdx.x] = expf(-Lmb[kap * (Dn + 1) + threadIdx.x]);
        if (threadIdx.x == Dn) s_amp = expf(Lmb[kap * (Dn + 1) + Dn]);
    }
    __syncthreads();
    if (o >= N0n || n >= Nn) return;
    float prod = 1.f, ssum = 0.f;
#pragma unroll
    for (int d = 0; d < Dn; d++) {
        float S = fabsf(to_[threadIdx.y][d] - tn_[threadIdx.x][d]) * s_ils[d];
        prod *= (1.f + S);
        ssum += S;
    }
    g_Knt[(size_t)(kap * N0n + o) * Nn + n] = s_amp * prod * fast_expn(ssum);
}

// ---------------- rhs init ----------------
__global__ void init_rhs_kernel(const float* __restrict__ Mu) {
    int idx = blockIdx.x * blockDim.x + threadIdx.x;
    if (idx >= KAPn * NPn) return;
    int kap = idx / NPn, i = idx % NPn;
    g_rhs[idx] = (i < Nn) ? Mu[kap * Nn + i] : 0.f;
}

// ---------------- potf2 v3: 32-wide blocking + broadcast-form chol32 ---------
// chol32: lane l owns row l; trailing update uses one shfl broadcast per column
// element -> 31-j INDEPENDENT update ops per step (no intra-lane LDS RAW chain).
__global__ void __launch_bounds__(512) potf2_kernel(const float* __restrict__ Lmb, int off) {
    extern __shared__ float sm[];
    float* sh = sm;                  // [128][129]
    float* sdi = sm + NBn * (NBn + 1);
    int kap = blockIdx.x;
    int tid = threadIdx.x;
    float* A = g_K + (size_t)kap * NPn * NPn + (size_t)off * NPn + off;
    for (int fi = tid; fi < 4096; fi += 512) {        // 128x128 in float4s
        int r = fi >> 5;
        int c4 = (fi & 31) * 4;
        float4 v = *(const float4*)(A + (size_t)r * NPn + c4);
        float* shr = sh + r * (NBn + 1) + c4;
        shr[0] = v.x; shr[1] = v.y; shr[2] = v.z; shr[3] = v.w;
    }
    __shared__ float s_dmin;
    if (tid == 0) s_dmin = 1e-4f * expf(Lmb[kap * (Dn + 1) + Dn]);
    __syncthreads();
    float dmin = s_dmin;

    for (int s = 0; s < 4; s++) {
        int c0 = s * 32;
        // ---- chol32 (warp 0): broadcast rank-1 form, direct scaling ----
        if (tid < 32) {
            int l = tid;
            float* myrow = sh + (size_t)(c0 + l) * (NBn + 1) + c0;
            for (int j = 0; j < 32; j++) {
                float dj = sh[(c0 + j) * (NBn + 1) + c0 + j];   // broadcast LDS
                if (!(dj > dmin)) dj = dmin;                    // clamp (+NaN guard)
                float rinv = rsqrtf(dj);
                float a = (l == j) ? dj : myrow[j];
                float lj = a * rinv;                            // L[l][j] (valid l>=j)
                myrow[j] = lj;                                  // finalize column j
                if (l == j) sdi[c0 + j] = rinv;
                for (int i = j + 1; i < 32; i++) {
                    float lij = __shfl_sync(0xffffffffu, lj, i);
                    if (l >= i) myrow[i] -= lj * lij;           // independent across i
                }
                __syncwarp();
            }
        }
        __syncthreads();

        int R = NBn - c0 - 32;            // in-block rows below
        if (R > 0) {
            // ---- trsm: 16 warps, nr rows each, lane = col ----
            int nr = R >> 4;              // 6 / 4 / 2
            int w = tid >> 5, lane = tid & 31;
            int row0 = c0 + 32 + w * nr;
            float x[6];
#pragma unroll
            for (int rr = 0; rr < 6; rr++)
                if (rr < nr) x[rr] = sh[(row0 + rr) * (NBn + 1) + c0 + lane];
            for (int j = 0; j < 32; j++) {
                float sv = sdi[c0 + j];
                float Lcol = sh[(c0 + lane) * (NBn + 1) + c0 + j];  // L[lane][j], lane>j
#pragma unroll
                for (int rr = 0; rr < 6; rr++) {
                    if (rr < nr) {
                        if (lane == j) x[rr] *= sv;
                        float xj = __shfl_sync(0xffffffffu, x[rr], j);
                        if (lane > j) x[rr] -= xj * Lcol;
                    }
                }
            }
#pragma unroll
            for (int rr = 0; rr < 6; rr++)
                if (rr < nr) sh[(row0 + rr) * (NBn + 1) + c0 + lane] = x[rr];
            __syncthreads();

            // ---- rank-32 syrk of trailing in-block region ----
            int t = tid & 127, q = tid >> 7;
            if (t >= c0 + 32) {
                float Lt[32];
#pragma unroll
                for (int j = 0; j < 32; j++) Lt[j] = sh[t * (NBn + 1) + c0 + j];
                int ilo = q * 32; if (ilo < c0 + 32) ilo = c0 + 32;
                int ihi = q * 32 + 31; if (ihi > t) ihi = t;
                for (int i = ilo; i <= ihi; i++) {
                    float acc = 0.f;
#pragma unroll
                    for (int j = 0; j < 32; j++) acc += Lt[j] * sh[i * (NBn + 1) + c0 + j];
                    sh[t * (NBn + 1) + i] -= acc;
                }
            }
            __syncthreads();
        }
    }

    for (int fi = tid; fi < 4096; fi += 512) {
        int r = fi >> 5;
        int c4 = (fi & 31) * 4;
        const float* shr = sh + r * (NBn + 1) + c4;
        float4 v = make_float4(shr[0], shr[1], shr[2], shr[3]);
        *(float4*)(A + (size_t)r * NPn + c4) = v;
    }
    if (tid < NBn) g_invd[kap * NPn + off + tid] = sdi[tid];
}

// ---------------- Cholesky panel trsm: L21 = A21 * L11^{-T} ----------------
// 32 rows per CTA (8 warps x 4 rows) — the proven configuration.
__global__ void __launch_bounds__(256) trsm_kernel(int off, int m) {
    extern __shared__ float sm[];
    float* Ls = sm;                  // [128][129]
    float* sinv = sm + NBn * (NBn + 1);
    int kap = blockIdx.y;
    int tid = threadIdx.x;
    float* G = g_K + (size_t)kap * NPn * NPn;
    const float* L11 = G + (size_t)off * NPn + off;
    for (int idx = tid; idx < NBn * NBn; idx += 256) {
        int r = idx >> 7, c = idx & 127;
        Ls[r * (NBn + 1) + c] = L11[r * NPn + c];
    }
    if (tid < NBn) sinv[tid] = g_invd[kap * NPn + off + tid];
    __syncthreads();
    int w = tid >> 5, lane = tid & 31;
    int row0 = off + NBn + blockIdx.x * 32 + w * 4;
    float x[4][4];                   // [row][quarter]
#pragma unroll
    for (int rr = 0; rr < 4; rr++) {
        const float* arow = G + (size_t)(row0 + rr) * NPn + off;
#pragma unroll
        for (int qq = 0; qq < 4; qq++) x[rr][qq] = arow[lane + 32 * qq];
    }
#pragma unroll
    for (int qj = 0; qj < 4; qj++) {
#pragma unroll
        for (int lj = 0; lj < 32; lj++) {
            int j = qj * 32 + lj;
            float sv = sinv[j];
            if (lane == lj) {
#pragma unroll
                for (int rr = 0; rr < 4; rr++) x[rr][qj] *= sv;
            }
            float xj[4];
#pragma unroll
            for (int rr = 0; rr < 4; rr++) xj[rr] = __shfl_sync(0xffffffffu, x[rr][qj], lj);
#pragma unroll
            for (int qq = qj; qq < 4; qq++) {
                float Lv = Ls[(lane + 32 * qq) * (NBn + 1) + j];
                bool act = (qq > qj) || (lane > lj);
                if (act) {
#pragma unroll
                    for (int rr = 0; rr < 4; rr++) x[rr][qq] -= xj[rr] * Lv;
                }
            }
        }
    }
#pragma unroll
    for (int rr = 0; rr < 4; rr++) {
        float* arow = G + (size_t)(row0 + rr) * NPn + off;
#pragma unroll
        for (int qq = 0; qq < 4; qq++) arow[lane + 32 * qq] = x[rr][qq];
    }
}

// ---------------- SYRK: conflict-free micro-tile + packed f32x2 FMA ----------
__global__ void __launch_bounds__(256, 2) syrk_kernel(int off, int nb) {
    int kap = blockIdx.y;
    int tt = blockIdx.x;
    int bi = 0, rem = tt;
    while (rem > bi) { rem -= (bi + 1); bi++; }
    int bj = rem;                     // bi >= bj
    int r0 = off + NBn;
    int R = r0 + bi * NBn, C = r0 + bj * NBn;
    float* G = g_K + (size_t)kap * NPn * NPn;

    __shared__ float As[KCH][NBn + 4];
    __shared__ float Bs[KCH][NBn + 4];
    unsigned long long acc2[8][4];
#pragma unroll
    for (int m = 0; m < 8; m++)
#pragma unroll
        for (int p = 0; p < 4; p++) acc2[m][p] = 0ull;

    int tid = threadIdx.x;
    int tr = tid >> 4, tc = tid & 15;

    for (int kk = 0; kk < NBn; kk += KCH) {
#pragma unroll
        for (int s = 0; s < 4; s++) {
            int fi = tid + s * 256;       // float4 index in [0,1024)
            int row = fi >> 3;
            int kq = (fi & 7) * 4;
            float4 av = *(const float4*)(G + (size_t)(R + row) * NPn + off + kk + kq);
            As[kq + 0][row] = av.x; As[kq + 1][row] = av.y;
            As[kq + 2][row] = av.z; As[kq + 3][row] = av.w;
            float4 bv = *(const float4*)(G + (size_t)(C + row) * NPn + off + kk + kq);
            Bs[kq + 0][row] = bv.x; Bs[kq + 1][row] = bv.y;
            Bs[kq + 2][row] = bv.z; Bs[kq + 3][row] = bv.w;
        }
        __syncthreads();
#pragma unroll
        for (int k = 0; k < KCH; k++) {
            float4 a0 = *(const float4*)&As[k][tr * 8];
            float4 a1 = *(const float4*)&As[k][tr * 8 + 4];
            ulonglong2 bl = *(const ulonglong2*)&Bs[k][tc * 4];
            ulonglong2 bh = *(const ulonglong2*)&Bs[k][tc * 4 + 64];
            float ar[8] = {a0.x, a0.y, a0.z, a0.w, a1.x, a1.y, a1.z, a1.w};
#pragma unroll
            for (int m = 0; m < 8; m++) {
                unsigned long long am = splat2(ar[m]);
                ffma2(acc2[m][0], am, bl.x);
                ffma2(acc2[m][1], am, bl.y);
                ffma2(acc2[m][2], am, bh.x);
                ffma2(acc2[m][3], am, bh.y);
            }
        }
        __syncthreads();
    }
#pragma unroll
    for (int m = 0; m < 8; m++) {
        float* rowp = G + (size_t)(R + tr * 8 + m) * NPn + C;
        float4* p0 = (float4*)(rowp + tc * 4);
        float4* p1 = (float4*)(rowp + tc * 4 + 64);
        float4 v0 = *p0, v1 = *p1;
        float e0, e1, e2, e3;
        unpack2(acc2[m][0], e0, e1); unpack2(acc2[m][1], e2, e3);
        v0.x -= e0; v0.y -= e1; v0.z -= e2; v0.w -= e3;
        unpack2(acc2[m][2], e0, e1); unpack2(acc2[m][3], e2, e3);
        v1.x -= e0; v1.y -= e1; v1.z -= e2; v1.w -= e3;
        *p0 = v0; *p1 = v1;
    }
}

// ---------------- fused forward solve: L y = rhs (one CTA per kap) ----------
__global__ void __launch_bounds__(1024) fwd_solve_kernel() {
    extern __shared__ float sm[];
    float* Ls = sm;                               // [128][129]
    float* sinv = sm + NBn * (NBn + 1);           // [128]
    float* sr = sinv + NBn;                       // [2048]
    int kap = blockIdx.x;
    int tid = threadIdx.x;
    const float* G = g_K + (size_t)kap * NPn * NPn;
    float* r = g_rhs + kap * NPn;
    for (int i = tid; i < NPn; i += 1024) sr[i] = r[i];
    for (int k = 0; k < NSTEPS; k++) {
        int off = k * NBn;
        const float* L11 = G + (size_t)off * NPn + off;
        for (int idx = tid; idx < NBn * NBn; idx += 1024) {
            int rr = idx >> 7, c = idx & 127;
            Ls[rr * (NBn + 1) + c] = L11[rr * NPn + c];
        }
        if (tid < NBn) sinv[tid] = g_invd[kap * NPn + off + tid];
        __syncthreads();
        if (tid < 32) {
            int lane = tid;
            float x[4];
#pragma unroll
            for (int qq = 0; qq < 4; qq++) x[qq] = sr[off + lane + 32 * qq];
#pragma unroll
            for (int qj = 0; qj < 4; qj++) {
#pragma unroll
                for (int lj = 0; lj < 32; lj++) {
                    int j = qj * 32 + lj;
                    if (lane == lj) x[qj] *= sinv[j];
                    float xj = __shfl_sync(0xffffffffu, x[qj], lj);
                    if (lane > lj) x[qj] -= xj * Ls[(lane + 32 * qj) * (NBn + 1) + j];
#pragma unroll
                    for (int qq = qj + 1; qq < 4; qq++)
                        x[qq] -= xj * Ls[(lane + 32 * qq) * (NBn + 1) + j];
                }
            }
#pragma unroll
            for (int qq = 0; qq < 4; qq++) sr[off + lane + 32 * qq] = x[qq];
        }
        __syncthreads();
        // update rows below: 4 rows in flight per warp (MLP=4), m % 128 == 0
        int wid = tid >> 5, lane = tid & 31;
        const float4* srv = (const float4*)(sr + off);
        float4 b = srv[lane];
        for (int row = off + NBn + wid; row < NPn; row += 128) {
            float4 a0 = ((const float4*)(G + (size_t)row * NPn + off))[lane];
            float4 a1 = ((const float4*)(G + (size_t)(row + 32) * NPn + off))[lane];
            float4 a2 = ((const float4*)(G + (size_t)(row + 64) * NPn + off))[lane];
            float4 a3 = ((const float4*)(G + (size_t)(row + 96) * NPn + off))[lane];
            float s0 = a0.x * b.x + a0.y * b.y + a0.z * b.z + a0.w * b.w;
            float s1 = a1.x * b.x + a1.y * b.y + a1.z * b.z + a1.w * b.w;
            float s2 = a2.x * b.x + a2.y * b.y + a2.z * b.z + a2.w * b.w;
            float s3 = a3.x * b.x + a3.y * b.y + a3.z * b.z + a3.w * b.w;
#pragma unroll
            for (int s = 16; s > 0; s >>= 1) {
                s0 += __shfl_xor_sync(0xffffffffu, s0, s);
                s1 += __shfl_xor_sync(0xffffffffu, s1, s);
                s2 += __shfl_xor_sync(0xffffffffu, s2, s);
                s3 += __shfl_xor_sync(0xffffffffu, s3, s);
            }
            if (lane == 0) {
                sr[row] -= s0;
                sr[row + 32] -= s1;
                sr[row + 64] -= s2;
                sr[row + 96] -= s3;
            }
        }
        __syncthreads();
    }
    for (int i = tid; i < NPn; i += 1024) r[i] = sr[i];
}

// ---------------- fused backward solve: L^T x = y (one CTA per kap) ---------
__global__ void __launch_bounds__(1024) bwd_solve_kernel() {
    extern __shared__ float sm[];
    float* Ls = sm;
    float* sinv = sm + NBn * (NBn + 1);
    float* sr = sinv + NBn;
    int kap = blockIdx.x;
    int tid = threadIdx.x;
    const float* G = g_K + (size_t)kap * NPn * NPn;
    float* r = g_rhs + kap * NPn;
    for (int i = tid; i < NPn; i += 1024) sr[i] = r[i];
    for (int k = NSTEPS - 1; k >= 0; k--) {
        int off = k * NBn;
        const float* L11 = G + (size_t)off * NPn + off;
        for (int idx = tid; idx < NBn * NBn; idx += 1024) {
            int rr = idx >> 7, c = idx & 127;
            Ls[rr * (NBn + 1) + c] = L11[rr * NPn + c];
        }
        if (tid < NBn) sinv[tid] = g_invd[kap * NPn + off + tid];
        __syncthreads();
        if (tid < 32) {
            int lane = tid;
            float x[4];
#pragma unroll
            for (int qq = 0; qq < 4; qq++) x[qq] = sr[off + lane + 32 * qq];
#pragma unroll
            for (int qj = 3; qj >= 0; qj--) {
#pragma unroll
                for (int lj = 31; lj >= 0; lj--) {
                    int j = qj * 32 + lj;
                    if (lane == lj) x[qj] *= sinv[j];
                    float xj = __shfl_sync(0xffffffffu, x[qj], lj);
                    if (lane < lj) x[qj] -= xj * Ls[j * (NBn + 1) + lane + 32 * qj];
#pragma unroll
                    for (int qq = 0; qq < qj; qq++)
                        x[qq] -= xj * Ls[j * (NBn + 1) + lane + 32 * qq];
                }
            }
#pragma unroll
            for (int qq = 0; qq < 4; qq++) sr[off + lane + 32 * qq] = x[qq];
        }
        __syncthreads();
        float4* srv = (float4*)sr;
        for (int c4 = tid; c4 < off / 4; c4 += 1024) {
            const float4* col = (const float4*)(G + (size_t)off * NPn) + c4;
            float4 s = make_float4(0.f, 0.f, 0.f, 0.f);
#pragma unroll 8
            for (int i = 0; i < NBn; i++) {
                float4 v = col[(size_t)i * (NPn / 4)];
                float xv = sr[off + i];
                s.x += v.x * xv; s.y += v.y * xv; s.z += v.z * xv; s.w += v.w * xv;
            }
            float4 cur = srv[c4];
            cur.x -= s.x; cur.y -= s.y; cur.z -= s.z; cur.w -= s.w;
            srv[c4] = cur;
        }
        __syncthreads();
    }
    for (int i = tid; i < NPn; i += 1024) r[i] = sr[i];
}

// ---------------- ghat = K_nt @ alpha (warp per output) ----------------
__global__ void ghat_kernel() {
    int gw = (blockIdx.x * blockDim.x + threadIdx.x) >> 5;
    int lane = threadIdx.x & 31;
    if (gw >= KAPn * N0n) return;
    int kap = gw / N0n, o = gw % N0n;
    const float* Kr = g_Knt + (size_t)(kap * N0n + o) * Nn;
    const float* a = g_rhs + kap * NPn;
    float s = 0.f;
    for (int i = lane * 4; i < Nn; i += 128) {
        float4 kv = *(const float4*)(Kr + i);
        float4 av = *(const float4*)(a + i);
        s += kv.x * av.x + kv.y * av.y + kv.z * av.z + kv.w * av.w;
    }
    s = warp_reduce(s);
    if (lane == 0) g_ghat[kap * N0n + o] = s;
}

// ---------------- fhat = psi + Phi @ ghat ----------------
__global__ void fhat_kernel(const float* __restrict__ psi,
                            const float* __restrict__ Phi,
                            float* __restrict__ out) {
    int idx = blockIdx.x * blockDim.x + threadIdx.x;
    if (idx >= Mn * N0n) return;
    int m = idx / N0n, o = idx % N0n;
    float s = psi[m];
#pragma unroll
    for (int k = 0; k < KAPn; k++) s += Phi[m * KAPn + k] * g_ghat[k * N0n + o];
    out[idx] = s;
}

// ---------------- host launch ----------------
extern "C" void kernel_launch(void* const* d_in, const int* in_sizes, int n_in,
                              void* d_out, int out_size) {
    const float* theta0 = (const float*)d_in[0];
    const float* Lmb    = (const float*)d_in[1];
    // d_in[2] = lsigma2 (unused by fhat)
    const float* Mu     = (const float*)d_in[3];
    const float* psi    = (const float*)d_in[4];
    const float* Phi    = (const float*)d_in[5];
    const float* theta  = (const float*)d_in[6];
    float* out = (float*)d_out;

    const int SMEM_FACT  = (NBn * (NBn + 1) + NBn) * (int)sizeof(float);          // 66560
    const int SMEM_SOLVE = (NBn * (NBn + 1) + NBn + NPn) * (int)sizeof(float);    // 74752
    cudaFuncSetAttribute(potf2_kernel,     cudaFuncAttributeMaxDynamicSharedMemorySize, SMEM_FACT);
    cudaFuncSetAttribute(trsm_kernel,      cudaFuncAttributeMaxDynamicSharedMemorySize, SMEM_FACT);
    cudaFuncSetAttribute(fwd_solve_kernel, cudaFuncAttributeMaxDynamicSharedMemorySize, SMEM_SOLVE);
    cudaFuncSetAttribute(bwd_solve_kernel, cudaFuncAttributeMaxDynamicSharedMemorySize, SMEM_SOLVE);

    // Launch order: #4 = potf2 step 0 (the profiled launch — measure the v3 chol32).
    build_ktt_kernel<<<dim3(NPn / 16, NPn / 16, KAPn), dim3(16, 16)>>>(theta, Lmb);
    build_knt_kernel<<<dim3((Nn + 15) / 16, (N0n + 15) / 16, KAPn), dim3(16, 16)>>>(theta0, theta, Lmb);
    init_rhs_kernel<<<(KAPn * NPn + 255) / 256, 256>>>(Mu);

    for (int k = 0; k < NSTEPS; k++) {
        int off = k * NBn;
        potf2_kernel<<<KAPn, 512, SMEM_FACT>>>(Lmb, off);   // k==0 -> launch #4
        int m = NPn - off - NBn;
        if (m > 0) {
            trsm_kernel<<<dim3(m / 32, KAPn), 256, SMEM_FACT>>>(off, m);
            int nb = m / NBn;
            syrk_kernel<<<dim3(nb * (nb + 1) / 2, KAPn), 256>>>(off, nb);
        }
    }

    fwd_solve_kernel<<<KAPn, 1024, SMEM_SOLVE>>>();
    bwd_solve_kernel<<<KAPn, 1024, SMEM_SOLVE>>>();

    ghat_kernel<<<(KAPn * N0n * 32 + 255) / 256, 256>>>();
    fhat_kernel<<<(Mn * N0n + 255) / 256, 256>>>(psi, Phi, out);
}